// round 3
// baseline (speedup 1.0000x reference)
#include <cuda_runtime.h>
#include <math_constants.h>

// Problem constants (fixed by the reference)
#define BB 2
#define TT 512
#define EE 1024
#define SS 2048
#define AA 30

#define BUCKET   16                   // start values per bucket
#define NBUCK    (TT / BUCKET)        // 32 buckets
#define ROWS_MAX (BUCKET + AA - 1)    // 45 rows touched by a bucket
#define EHALF    512                  // columns handled per block
#define C2       (EHALF / 2)          // 256 float2 columns per row

// smem: x tile [ROWS_MAX][C2] float2  +  span list [SS] int
#define SMEM_BYTES (ROWS_MAX * C2 * 8 + SS * 4)

__device__ float g_scores[BB * TT];
__device__ float g_probs[BB * SS * 32];

// ---------------------------------------------------------------------------
// Kernel 1: scores[b,t] = relu(dot(x[b,t,:], W) + bias). One warp per row.
// ---------------------------------------------------------------------------
__global__ void score_kernel(const float* __restrict__ x,
                             const float* __restrict__ W,
                             const float* __restrict__ bias) {
    const int row  = blockIdx.x * 8 + (threadIdx.x >> 5);   // B*T = 1024 rows
    const int lane = threadIdx.x & 31;

    const float4* __restrict__ xr = reinterpret_cast<const float4*>(x + (size_t)row * EE);
    const float4* __restrict__ w4 = reinterpret_cast<const float4*>(W);

    float acc = 0.0f;
#pragma unroll
    for (int i = 0; i < 8; ++i) {
        const float4 xv = xr[lane + i * 32];
        const float4 wv = w4[lane + i * 32];
        acc += xv.x * wv.x + xv.y * wv.y + xv.z * wv.z + xv.w * wv.w;
    }
#pragma unroll
    for (int off = 16; off; off >>= 1)
        acc += __shfl_xor_sync(0xffffffffu, acc, off);

    if (lane == 0)
        g_scores[row] = fmaxf(acc + bias[0], 0.0f);
}

// ---------------------------------------------------------------------------
// Kernel 2: softmax probs per (b, s) -> g_probs[b][s][0..31] (0 for lane >= w)
// One warp per (b, s).
// ---------------------------------------------------------------------------
__global__ __launch_bounds__(256)
void prob_kernel(const int* __restrict__ start,
                 const int* __restrict__ end) {
    const int wid  = blockIdx.x * 8 + (threadIdx.x >> 5);   // 0 .. B*S-1
    const int lane = threadIdx.x & 31;
    const int s = wid & (SS - 1);
    const int b = wid >> 11;

    const int t0 = start[s];
    const int w  = end[s] - t0 + 1;                          // 1..30

    float sc = (lane < w) ? g_scores[b * TT + t0 + lane] : -CUDART_INF_F;
    float m = sc;
#pragma unroll
    for (int off = 16; off; off >>= 1)
        m = fmaxf(m, __shfl_xor_sync(0xffffffffu, m, off));
    float e = (lane < w) ? __expf(sc - m) : 0.0f;
    float sum = e;
#pragma unroll
    for (int off = 16; off; off >>= 1)
        sum += __shfl_xor_sync(0xffffffffu, sum, off);

    g_probs[((size_t)b * SS + s) * 32 + lane] = e / sum;
}

// ---------------------------------------------------------------------------
// Kernel 3: bucketed span pooling served from shared memory.
// Block = (bucket kb, E-half h, batch b). Loads x rows [16kb, 16kb+45) for its
// E-half into smem once, finds all spans with start in the bucket, then each
// span: out = sum_j p_j * xs[t0-base+j][:]  (pure LDS traffic).
// ---------------------------------------------------------------------------
extern __shared__ char smem_raw[];

__global__ __launch_bounds__(256)
void span_bucket_kernel(const float* __restrict__ x,
                        const int* __restrict__ start,
                        const int* __restrict__ end,
                        float* __restrict__ out) {
    float2* xs   = reinterpret_cast<float2*>(smem_raw);                       // [ROWS_MAX][C2]
    int*    list = reinterpret_cast<int*>(smem_raw + ROWS_MAX * C2 * 8);      // [SS]
    __shared__ int cnt;

    const int tid  = threadIdx.x;
    const int lane = tid & 31;
    const int kb   = blockIdx.x;          // bucket
    const int h    = blockIdx.y;          // E-half
    const int b    = blockIdx.z;          // batch
    const int base = kb * BUCKET;

    if (tid == 0) cnt = 0;
    __syncthreads();

    // ---- scan start[] and collect this bucket's spans ----
#pragma unroll
    for (int i = 0; i < SS / 256; ++i) {
        const int s  = tid + i * 256;
        const unsigned d = (unsigned)(start[s] - base);
        if (d < BUCKET) {
            const int pos = atomicAdd(&cnt, 1);
            list[pos] = s;
        }
    }

    // ---- load x tile into smem (rows base .. base+nr-1, this E-half) ----
    const int nr = min(ROWS_MAX, TT - base);
    const float4* __restrict__ x4 =
        reinterpret_cast<const float4*>(x + ((size_t)b * TT + base) * EE + h * EHALF);
    float4* xs4 = reinterpret_cast<float4*>(xs);   // row stride 128 float4
    for (int i = tid; i < nr * 128; i += 256) {
        const int r = i >> 7;
        const int c = i & 127;
        xs4[r * 128 + c] = x4[(size_t)r * 256 + c];   // gmem row stride EE/4=256
    }
    __syncthreads();

    const int n = cnt;

    // ---- serve spans from smem ----
    for (int idx = 0; idx < n; ++idx) {
        const int s  = list[idx];
        const int t0 = start[s];
        const int w  = end[s] - t0 + 1;
        const int r0 = t0 - base;

        // lane j holds p_j for this span
        const float pl = g_probs[((size_t)b * SS + s) * 32 + lane];

        float2 acc = make_float2(0.0f, 0.0f);
        int j = 0;
#pragma unroll 1
        for (; j + 4 <= w; j += 4) {
            const float p0 = __shfl_sync(0xffffffffu, pl, j);
            const float p1 = __shfl_sync(0xffffffffu, pl, j + 1);
            const float p2 = __shfl_sync(0xffffffffu, pl, j + 2);
            const float p3 = __shfl_sync(0xffffffffu, pl, j + 3);
            const float2 v0 = xs[(r0 + j)     * C2 + tid];
            const float2 v1 = xs[(r0 + j + 1) * C2 + tid];
            const float2 v2 = xs[(r0 + j + 2) * C2 + tid];
            const float2 v3 = xs[(r0 + j + 3) * C2 + tid];
            acc.x += p0 * v0.x + p1 * v1.x + p2 * v2.x + p3 * v3.x;
            acc.y += p0 * v0.y + p1 * v1.y + p2 * v2.y + p3 * v3.y;
        }
        for (; j < w; ++j) {
            const float pj = __shfl_sync(0xffffffffu, pl, j);
            const float2 v = xs[(r0 + j) * C2 + tid];
            acc.x += pj * v.x;
            acc.y += pj * v.y;
        }

        float2* __restrict__ o =
            reinterpret_cast<float2*>(out + ((size_t)b * SS + s) * EE + h * EHALF);
        o[tid] = acc;
    }
}

// ---------------------------------------------------------------------------
// Launch
// Inputs (metadata order): x (B,T,E) f32, W (E,1) f32, b (1,) f32,
//                          start (S,) i32, end (S,) i32
// Output: (B, S, E) f32
// ---------------------------------------------------------------------------
extern "C" void kernel_launch(void* const* d_in, const int* in_sizes, int n_in,
                              void* d_out, int out_size) {
    const float* x     = (const float*)d_in[0];
    const float* W     = (const float*)d_in[1];
    const float* bias  = (const float*)d_in[2];
    const int*   start = (const int*)d_in[3];
    const int*   end   = (const int*)d_in[4];
    float*       out   = (float*)d_out;

    static bool attr_done = false;
    if (!attr_done) {
        cudaFuncSetAttribute(span_bucket_kernel,
                             cudaFuncAttributeMaxDynamicSharedMemorySize,
                             SMEM_BYTES);
        attr_done = true;
    }

    // Kernel 1: scores
    score_kernel<<<(BB * TT) / 8, 256>>>(x, W, bias);

    // Kernel 2: softmax probs, one warp per (b,s)
    prob_kernel<<<(BB * SS) / 8, 256>>>(start, end);

    // Kernel 3: bucketed pooling
    dim3 grid(NBUCK, EE / EHALF, BB);
    span_bucket_kernel<<<grid, 256, SMEM_BYTES>>>(x, start, end, out);
}

// round 4
// speedup vs baseline: 1.9262x; 1.9262x over previous
#include <cuda_runtime.h>
#include <math_constants.h>

// Problem constants (fixed by the reference)
#define BB 2
#define TT 512
#define EE 1024
#define SS 2048
#define AA 30

#define BUCKET   16                   // start values per bucket
#define NBUCK    (TT / BUCKET)        // 32 buckets
#define ROWS_MAX (BUCKET + AA - 1)    // 45 rows touched by a bucket
#define EHALF    512                  // columns handled per block
#define C4       (EHALF / 4)          // 128 float4 columns per row

// smem: x tile [ROWS_MAX][C4] float4  +  span list [SS] int
#define SMEM_BYTES (ROWS_MAX * C4 * 16 + SS * 4)

__device__ float g_scores[BB * TT];

// ---------------------------------------------------------------------------
// Kernel 1: scores[b,t] = relu(dot(x[b,t,:], W) + bias).
// One BLOCK per row (1024 blocks): 256 threads x float4 = 1024 floats.
// ---------------------------------------------------------------------------
__global__ __launch_bounds__(256)
void score_kernel(const float* __restrict__ x,
                  const float* __restrict__ W,
                  const float* __restrict__ bias) {
    __shared__ float red[8];
    const int row  = blockIdx.x;
    const int tid  = threadIdx.x;
    const int lane = tid & 31;
    const int wrp  = tid >> 5;

    const float4 xv = reinterpret_cast<const float4*>(x)[(size_t)row * 256 + tid];
    const float4 wv = reinterpret_cast<const float4*>(W)[tid];
    float acc = xv.x * wv.x + xv.y * wv.y + xv.z * wv.z + xv.w * wv.w;

#pragma unroll
    for (int off = 16; off; off >>= 1)
        acc += __shfl_xor_sync(0xffffffffu, acc, off);
    if (lane == 0) red[wrp] = acc;
    __syncthreads();

    if (tid == 0) {
        float s = red[0];
#pragma unroll
        for (int i = 1; i < 8; ++i) s += red[i];
        g_scores[row] = fmaxf(s + bias[0], 0.0f);
    }
}

// ---------------------------------------------------------------------------
// Kernel 2: bucketed span pooling, WARP-per-span served from a shared tile.
// Block = (bucket kb, E-half h, batch b), 128 blocks total (one wave).
//   1. all threads: scan start[] -> smem list of this bucket's spans
//   2. all threads: load x rows [16kb, 16kb+45) x EHALF into smem
//   3. each WARP independently: pick spans list[warp], list[warp+8], ...
//      in-warp softmax from g_scores, then out = sum_j p_j * tile_row(j)
//      (4 float4 per lane, LDS-only inner loop, unrolled x2 for MLP)
// ---------------------------------------------------------------------------
extern __shared__ char smem_raw[];

__global__ __launch_bounds__(256)
void span_tile_kernel(const float* __restrict__ x,
                      const int* __restrict__ start,
                      const int* __restrict__ end,
                      float* __restrict__ out) {
    float4* xs   = reinterpret_cast<float4*>(smem_raw);                   // [ROWS_MAX][C4]
    int*    list = reinterpret_cast<int*>(smem_raw + ROWS_MAX * C4 * 16); // [SS]
    __shared__ int cnt;

    const int tid  = threadIdx.x;
    const int lane = tid & 31;
    const int wrp  = tid >> 5;
    const int kb   = blockIdx.x;          // bucket
    const int h    = blockIdx.y;          // E-half
    const int b    = blockIdx.z;          // batch
    const int base = kb * BUCKET;

    if (tid == 0) cnt = 0;
    __syncthreads();

    // ---- collect this bucket's spans ----
#pragma unroll
    for (int i = 0; i < SS / 256; ++i) {
        const int s = tid + i * 256;
        const unsigned d = (unsigned)(start[s] - base);
        if (d < BUCKET) {
            const int pos = atomicAdd(&cnt, 1);
            list[pos] = s;
        }
    }

    // ---- load x tile into smem (rows base .. base+nr-1, this E-half) ----
    const int nr = min(ROWS_MAX, TT - base);
    const float4* __restrict__ x4 =
        reinterpret_cast<const float4*>(x + ((size_t)b * TT + base) * EE + h * EHALF);
    for (int i = tid; i < nr * C4; i += 256) {
        const int r = i >> 7;            // / C4 (=128)
        const int c = i & (C4 - 1);
        xs[r * C4 + c] = x4[(size_t)r * (EE / 4) + c];
    }
    __syncthreads();

    const int n = cnt;
    const float* __restrict__ scores_b = g_scores + b * TT;

    // ---- each warp serves spans independently ----
    for (int idx = wrp; idx < n; idx += 8) {
        const int s  = list[idx];
        const int t0 = start[s];
        const int w  = end[s] - t0 + 1;   // 1..30
        const int r0 = t0 - base;

        // in-warp softmax: lane j holds p_j (0 for lane >= w)
        float sc = (lane < w) ? scores_b[t0 + lane] : -CUDART_INF_F;
        float m = sc;
#pragma unroll
        for (int off = 16; off; off >>= 1)
            m = fmaxf(m, __shfl_xor_sync(0xffffffffu, m, off));
        float e = (lane < w) ? __expf(sc - m) : 0.0f;
        float sum = e;
#pragma unroll
        for (int off = 16; off; off >>= 1)
            sum += __shfl_xor_sync(0xffffffffu, sum, off);
        const float p = e / sum;

        float4 acc[4];
#pragma unroll
        for (int k = 0; k < 4; ++k)
            acc[k] = make_float4(0.0f, 0.0f, 0.0f, 0.0f);

        int j = 0;
#pragma unroll 1
        for (; j + 2 <= w; j += 2) {
            const float p0 = __shfl_sync(0xffffffffu, p, j);
            const float p1 = __shfl_sync(0xffffffffu, p, j + 1);
            const float4* row0 = xs + (r0 + j)     * C4;
            const float4* row1 = xs + (r0 + j + 1) * C4;
            float4 v0[4], v1[4];
#pragma unroll
            for (int k = 0; k < 4; ++k) { v0[k] = row0[lane + 32 * k]; v1[k] = row1[lane + 32 * k]; }
#pragma unroll
            for (int k = 0; k < 4; ++k) {
                acc[k].x += p0 * v0[k].x + p1 * v1[k].x;
                acc[k].y += p0 * v0[k].y + p1 * v1[k].y;
                acc[k].z += p0 * v0[k].z + p1 * v1[k].z;
                acc[k].w += p0 * v0[k].w + p1 * v1[k].w;
            }
        }
        if (j < w) {
            const float pj = __shfl_sync(0xffffffffu, p, j);
            const float4* row = xs + (r0 + j) * C4;
#pragma unroll
            for (int k = 0; k < 4; ++k) {
                const float4 v = row[lane + 32 * k];
                acc[k].x += pj * v.x;
                acc[k].y += pj * v.y;
                acc[k].z += pj * v.z;
                acc[k].w += pj * v.w;
            }
        }

        float4* __restrict__ o =
            reinterpret_cast<float4*>(out + ((size_t)b * SS + s) * EE + h * EHALF);
#pragma unroll
        for (int k = 0; k < 4; ++k)
            o[lane + 32 * k] = acc[k];
    }
}

// ---------------------------------------------------------------------------
// Launch
// Inputs (metadata order): x (B,T,E) f32, W (E,1) f32, b (1,) f32,
//                          start (S,) i32, end (S,) i32
// Output: (B, S, E) f32
// ---------------------------------------------------------------------------
extern "C" void kernel_launch(void* const* d_in, const int* in_sizes, int n_in,
                              void* d_out, int out_size) {
    const float* x     = (const float*)d_in[0];
    const float* W     = (const float*)d_in[1];
    const float* bias  = (const float*)d_in[2];
    const int*   start = (const int*)d_in[3];
    const int*   end   = (const int*)d_in[4];
    float*       out   = (float*)d_out;

    static bool attr_done = false;
    if (!attr_done) {
        cudaFuncSetAttribute(span_tile_kernel,
                             cudaFuncAttributeMaxDynamicSharedMemorySize,
                             SMEM_BYTES);
        attr_done = true;
    }

    // Kernel 1: scores, one block per row
    score_kernel<<<BB * TT, 256>>>(x, W, bias);

    // Kernel 2: bucketed pooling, warp-per-span
    dim3 grid(NBUCK, EE / EHALF, BB);
    span_tile_kernel<<<grid, 256, SMEM_BYTES>>>(x, start, end, out);
}

// round 5
// speedup vs baseline: 2.0959x; 1.0881x over previous
#include <cuda_runtime.h>
#include <math_constants.h>

// Problem constants (fixed by the reference)
#define BB 2
#define TT 512
#define EE 1024
#define SS 2048
#define AA 30

#define BUCKET   16                   // start values per bucket
#define NBUCK    (TT / BUCKET)        // 32 buckets
#define ROWS_MAX (BUCKET + AA - 1)    // 45 rows touched by a bucket
#define EQ       128                  // columns handled per block (E/8)
#define NH       (EE / EQ)            // 8 E-slices
#define C4Q      (EQ / 4)             // 32 float4 per row

// smem: x tile [ROWS_MAX][C4Q] float4 (23040 B) + span list [SS] int (8192 B)
#define TILE_BYTES (ROWS_MAX * C4Q * 16)
#define SMEM_BYTES (TILE_BYTES + SS * 4)

__device__ float g_scores[BB * TT];

// ---------------------------------------------------------------------------
// Kernel 1: scores[b,t] = relu(dot(x[b,t,:], W) + bias).
// One BLOCK per row (1024 blocks): 256 threads x float4 = 1024 floats.
// ---------------------------------------------------------------------------
__global__ __launch_bounds__(256)
void score_kernel(const float* __restrict__ x,
                  const float* __restrict__ W,
                  const float* __restrict__ bias) {
    __shared__ float red[8];
    const int row  = blockIdx.x;
    const int tid  = threadIdx.x;
    const int lane = tid & 31;
    const int wrp  = tid >> 5;

    const float4 xv = reinterpret_cast<const float4*>(x)[(size_t)row * 256 + tid];
    const float4 wv = reinterpret_cast<const float4*>(W)[tid];
    float acc = xv.x * wv.x + xv.y * wv.y + xv.z * wv.z + xv.w * wv.w;

#pragma unroll
    for (int off = 16; off; off >>= 1)
        acc += __shfl_xor_sync(0xffffffffu, acc, off);
    if (lane == 0) red[wrp] = acc;
    __syncthreads();

    if (tid == 0) {
        float s = red[0];
#pragma unroll
        for (int i = 1; i < 8; ++i) s += red[i];
        g_scores[row] = fmaxf(s + bias[0], 0.0f);
    }
}

// ---------------------------------------------------------------------------
// Kernel 2: bucketed span pooling, warp-per-span from a small shared tile.
// Block = (bucket kb, E-slice h, batch b) -> 32*8*2 = 512 blocks, 31 KB smem
// each => ~3.5 blocks/SM, high occupancy. Each warp handles EQ=128 floats
// (1 float4/lane) for its spans; inner loop is 1 LDS.128 + shfl + 4 FMA/row.
// ---------------------------------------------------------------------------
extern __shared__ char smem_raw[];

__global__ __launch_bounds__(256)
void span_tile_kernel(const float* __restrict__ x,
                      const int* __restrict__ start,
                      const int* __restrict__ end,
                      float* __restrict__ out) {
    float4* xs   = reinterpret_cast<float4*>(smem_raw);              // [ROWS_MAX][C4Q]
    int*    list = reinterpret_cast<int*>(smem_raw + TILE_BYTES);    // [SS]
    __shared__ int cnt;

    const int tid  = threadIdx.x;
    const int lane = tid & 31;
    const int wrp  = tid >> 5;
    const int kb   = blockIdx.x;          // bucket
    const int h    = blockIdx.y;          // E-slice
    const int b    = blockIdx.z;          // batch
    const int base = kb * BUCKET;

    if (tid == 0) cnt = 0;
    __syncthreads();

    // ---- collect this bucket's spans into smem list ----
#pragma unroll
    for (int i = 0; i < SS / 256; ++i) {
        const int s = tid + i * 256;
        const unsigned d = (unsigned)(start[s] - base);
        if (d < BUCKET) {
            const int pos = atomicAdd(&cnt, 1);
            list[pos] = s;
        }
    }

    // ---- load x tile (rows base..base+nr-1, this E-slice) into smem ----
    const int nr = min(ROWS_MAX, TT - base);
    const float4* __restrict__ x4 =
        reinterpret_cast<const float4*>(x + ((size_t)b * TT + base) * EE + h * EQ);
    for (int i = tid; i < nr * C4Q; i += 256) {
        const int r = i >> 5;             // / C4Q (=32)
        const int c = i & (C4Q - 1);
        xs[r * C4Q + c] = x4[(size_t)r * (EE / 4) + c];
    }
    __syncthreads();

    const int n = cnt;
    const float* __restrict__ scores_b = g_scores + b * TT;

    // ---- each warp serves spans independently ----
    for (int idx = wrp; idx < n; idx += 8) {
        const int s  = list[idx];
        const int t0 = start[s];
        const int w  = end[s] - t0 + 1;   // 1..30
        const int r0 = t0 - base;

        // in-warp softmax: lane j holds p_j (0 for lane >= w)
        float sc = (lane < w) ? scores_b[t0 + lane] : -CUDART_INF_F;
        float m = sc;
#pragma unroll
        for (int off = 16; off; off >>= 1)
            m = fmaxf(m, __shfl_xor_sync(0xffffffffu, m, off));
        float e = (lane < w) ? __expf(sc - m) : 0.0f;
        float sum = e;
#pragma unroll
        for (int off = 16; off; off >>= 1)
            sum += __shfl_xor_sync(0xffffffffu, sum, off);
        const float p = e / sum;

        float4 acc = make_float4(0.0f, 0.0f, 0.0f, 0.0f);

        const float4* __restrict__ row = xs + r0 * C4Q + lane;
        int j = 0;
#pragma unroll 1
        for (; j + 2 <= w; j += 2) {
            const float p0 = __shfl_sync(0xffffffffu, p, j);
            const float p1 = __shfl_sync(0xffffffffu, p, j + 1);
            const float4 v0 = row[(j)     * C4Q];
            const float4 v1 = row[(j + 1) * C4Q];
            acc.x += p0 * v0.x + p1 * v1.x;
            acc.y += p0 * v0.y + p1 * v1.y;
            acc.z += p0 * v0.z + p1 * v1.z;
            acc.w += p0 * v0.w + p1 * v1.w;
        }
        if (j < w) {
            const float pj = __shfl_sync(0xffffffffu, p, j);
            const float4 v = row[j * C4Q];
            acc.x += pj * v.x;
            acc.y += pj * v.y;
            acc.z += pj * v.z;
            acc.w += pj * v.w;
        }

        reinterpret_cast<float4*>(out + ((size_t)b * SS + s) * EE + h * EQ)[lane] = acc;
    }
}

// ---------------------------------------------------------------------------
// Launch
// Inputs (metadata order): x (B,T,E) f32, W (E,1) f32, b (1,) f32,
//                          start (S,) i32, end (S,) i32
// Output: (B, S, E) f32
// ---------------------------------------------------------------------------
extern "C" void kernel_launch(void* const* d_in, const int* in_sizes, int n_in,
                              void* d_out, int out_size) {
    const float* x     = (const float*)d_in[0];
    const float* W     = (const float*)d_in[1];
    const float* bias  = (const float*)d_in[2];
    const int*   start = (const int*)d_in[3];
    const int*   end   = (const int*)d_in[4];
    float*       out   = (float*)d_out;

    // Kernel 1: scores, one block per row
    score_kernel<<<BB * TT, 256>>>(x, W, bias);

    // Kernel 2: bucketed pooling, warp-per-span, small tiles, high occupancy
    dim3 grid(NBUCK, NH, BB);
    span_tile_kernel<<<grid, 256, SMEM_BYTES>>>(x, start, end, out);
}